// round 11
// baseline (speedup 1.0000x reference)
#include <cuda_runtime.h>
#include <cuda_fp16.h>
#include <cstdint>

#define BB 2
#define SLQ 2048
#define SLK 2048
#define DM 1024
#define NH 16
#define DH 64
#define MROWS (BB*SLQ)   // 4096

// Scratch (allocation-free rule: device globals)
__device__ __half g_qh[NH*BB*SLQ*DH];
__device__ __half g_kh[NH*BB*SLK*DH];
__device__ __half g_vh[NH*BB*SLK*DH];
__device__ __half g_oh[NH*BB*SLQ*DH];
__device__ __half g_xq[MROWS*DM];
__device__ __half g_xk[MROWS*DM];
__device__ __half g_xv[MROWS*DM];
__device__ __half g_wq[NH*DM*DH];
__device__ __half g_wk[NH*DM*DH];
__device__ __half g_wv[NH*DM*DH];
__device__ __half g_wo[DM*DM];
__device__ float  g_x [MROWS*DM];
__device__ unsigned int g_mbits[BB*SLQ*(SLK/32)];

// ---------------------------------------------------------------------------
__device__ __forceinline__ unsigned pack2(float a, float b) {
    __half2 h = __floats2half2_rn(a, b);
    return *(unsigned*)&h;
}

__device__ __forceinline__ unsigned ex2h2(unsigned x) {
    unsigned r;
    asm("ex2.approx.f16x2 %0, %1;" : "=r"(r) : "r"(x));
    return r;
}

__device__ __forceinline__ unsigned hmul2(unsigned a, unsigned b) {
    unsigned r;
    asm("mul.f16x2 %0, %1, %2;" : "=r"(r) : "r"(a), "r"(b));
    return r;
}

__device__ __forceinline__ float ex2f(float x) {
    float r;
    asm("ex2.approx.f32 %0, %1;" : "=f"(r) : "f"(x));
    return r;
}

__device__ __forceinline__ void mma16816(float* c,
    unsigned a0, unsigned a1, unsigned a2, unsigned a3,
    unsigned b0, unsigned b1)
{
    asm volatile(
        "mma.sync.aligned.m16n8k16.row.col.f32.f16.f16.f32 "
        "{%0,%1,%2,%3}, {%4,%5,%6,%7}, {%8,%9}, {%0,%1,%2,%3};"
        : "+f"(c[0]), "+f"(c[1]), "+f"(c[2]), "+f"(c[3])
        : "r"(a0), "r"(a1), "r"(a2), "r"(a3), "r"(b0), "r"(b1));
}

__device__ __forceinline__ void ldsm4(unsigned& r0, unsigned& r1,
                                      unsigned& r2, unsigned& r3, unsigned addr)
{
    asm volatile("ldmatrix.sync.aligned.m8n8.x4.shared.b16 {%0,%1,%2,%3}, [%4];"
        : "=r"(r0), "=r"(r1), "=r"(r2), "=r"(r3) : "r"(addr));
}

__device__ __forceinline__ void ldsm4t(unsigned& r0, unsigned& r1,
                                       unsigned& r2, unsigned& r3, unsigned addr)
{
    asm volatile("ldmatrix.sync.aligned.m8n8.x4.trans.shared.b16 {%0,%1,%2,%3}, [%4];"
        : "=r"(r0), "=r"(r1), "=r"(r2), "=r"(r3) : "r"(addr));
}

__device__ __forceinline__ void cp16(unsigned smem, const void* gptr)
{
    asm volatile("cp.async.cg.shared.global [%0], [%1], 16;" :: "r"(smem), "l"(gptr));
}
__device__ __forceinline__ void cp_commit() { asm volatile("cp.async.commit_group;"); }
__device__ __forceinline__ void cp_wait0()  { asm volatile("cp.async.wait_group 0;"); }

// ---------------------------------------------------------------------------
// Fused prep: regions 0-6 fp32->fp16 conversion; region 7 packs the mask into
// bits (bit=1 -> masked). Mask dtype sniffed per-block: int32 bool words are
// all in {0,1}; uint8 bool bytes yield words >1 within the first 16K words.
// ---------------------------------------------------------------------------
__global__ void prep_kernel(
    const float* __restrict__ s0, const float* __restrict__ s1,
    const float* __restrict__ s2, const float* __restrict__ s3,
    const float* __restrict__ s4, const float* __restrict__ s5,
    const float* __restrict__ s6, const void* __restrict__ mraw)
{
    if (blockIdx.y == 7) {
        __shared__ int s_u8;
        const int lane = threadIdx.x & 31;
        if (threadIdx.x == 0) s_u8 = 0;
        __syncthreads();
        {
            const unsigned int* mw = (const unsigned int*)mraw;
            int found = 0;
            for (int i = threadIdx.x; i < 16384; i += blockDim.x)
                if (mw[i] > 1u) { found = 1; break; }
            if (found) s_u8 = 1;
        }
        __syncthreads();
        const bool u8 = (s_u8 != 0);

        const int nwords = BB * SLQ * (SLK / 32);
        int gw = (blockIdx.x * blockDim.x + threadIdx.x) >> 5;
        const int stride = (gridDim.x * blockDim.x) >> 5;
        for (int w = gw; w < nwords; w += stride) {
            int idx = w * 32 + lane;
            int v = u8 ? (int)((const unsigned char*)mraw)[idx]
                       : ((const int*)mraw)[idx];
            unsigned int bits = __ballot_sync(0xffffffffu, v != 0);
            if (lane == 0) g_mbits[w] = bits;
        }
        return;
    }

    const float* src;
    __half* dst;
    int n;
    switch (blockIdx.y) {
        case 0: src = s0; dst = g_xq; n = MROWS * DM; break;
        case 1: src = s1; dst = g_xk; n = MROWS * DM; break;
        case 2: src = s2; dst = g_xv; n = MROWS * DM; break;
        case 3: src = s3; dst = g_wq; n = NH * DM * DH; break;
        case 4: src = s4; dst = g_wk; n = NH * DM * DH; break;
        case 5: src = s5; dst = g_wv; n = NH * DM * DH; break;
        default: src = s6; dst = g_wo; n = DM * DM; break;
    }
    int i = (blockIdx.x * blockDim.x + threadIdx.x) * 4;
    int stride = gridDim.x * blockDim.x * 4;
    for (; i < n; i += stride) {
        float4 v = *(const float4*)&src[i];
        *(uint2*)&dst[i] = make_uint2(pack2(v.x, v.y), pack2(v.z, v.w));
    }
}

// ---------------------------------------------------------------------------
// Projection GEMM (fp16 mma): C[h,b,l,e] = sum_d X[b,l,d]*W[h,d,e]
// Block 128(M) x 128(N = 2 heads), k-tile 64, cp.async double buffered.
// ---------------------------------------------------------------------------
#define ASZ (128*72)
#define BSZ (64*136)
#define GEMM_SMEM ((2*ASZ + 2*BSZ) * 2)

__global__ __launch_bounds__(256, 2) void proj_kernel()
{
    extern __shared__ __half dsm[];
    __half* Asm = dsm;
    __half* Bsm = dsm + 2 * ASZ;

    const __half* __restrict__ X;
    const __half* __restrict__ W;
    __half* __restrict__ C;
    if (blockIdx.z == 0)      { X = g_xq; W = g_wq; C = g_qh; }
    else if (blockIdx.z == 1) { X = g_xk; W = g_wk; C = g_kh; }
    else                      { X = g_xv; W = g_wv; C = g_vh; }

    const int t = threadIdx.x;
    const int warp = t >> 5, lane = t & 31;
    const int g = lane >> 2, tq = lane & 3;
    const int wm = warp >> 2, wn = warp & 3;
    const int mBase = blockIdx.y * 128;
    const int h0 = blockIdx.x * 2;

    const int i8 = lane & 7, sel = lane >> 3;
    const int rowF = ((sel & 1) << 3) + i8;
    const int colF = (sel >> 1) << 3;
    const unsigned aSm = (unsigned)__cvta_generic_to_shared(Asm);
    const unsigned bSm = (unsigned)__cvta_generic_to_shared(Bsm);

    float acc[4][4][4];
    #pragma unroll
    for (int mt = 0; mt < 4; mt++)
        #pragma unroll
        for (int nt = 0; nt < 4; nt++)
            #pragma unroll
            for (int i = 0; i < 4; i++) acc[mt][nt][i] = 0.f;

    const int arow = t >> 3, aseg = (t & 7) * 8;
    const int brow = t >> 4, bseg = (t & 15) * 8;

    auto stage = [&](int kt, int buf) {
        #pragma unroll
        for (int it = 0; it < 4; it++) {
            int row = arow + it * 32;
            cp16(aSm + ((buf * 128 + row) * 72 + aseg) * 2,
                 &X[(size_t)(mBase + row) * DM + kt + aseg]);
        }
        #pragma unroll
        for (int it = 0; it < 4; it++) {
            int row = brow + it * 16;
            int head = h0 + (bseg >> 6), e = bseg & 63;
            cp16(bSm + ((buf * 64 + row) * 136 + bseg) * 2,
                 &W[((size_t)head * DM + kt + row) * DH + e]);
        }
        cp_commit();
    };

    stage(0, 0);
    const int NKT = DM / 64;  // 16
    for (int it = 0; it < NKT; it++) {
        cp_wait0();
        __syncthreads();
        if (it + 1 < NKT) stage((it + 1) * 64, (it + 1) & 1);
        const int abuf = (it & 1) * 128, bbuf = (it & 1) * 64;

        #pragma unroll
        for (int ks = 0; ks < 4; ks++) {
            unsigned af[4][4];
            #pragma unroll
            for (int mt = 0; mt < 4; mt++)
                ldsm4(af[mt][0], af[mt][1], af[mt][2], af[mt][3],
                      aSm + ((abuf + wm * 64 + mt * 16 + rowF) * 72 + ks * 16 + colF) * 2);
            #pragma unroll
            for (int ntp = 0; ntp < 2; ntp++) {
                unsigned b0, b1, b2, b3;
                ldsm4t(b0, b1, b2, b3,
                       bSm + ((bbuf + ks * 16 + rowF) * 136 + wn * 32 + ntp * 16 + colF) * 2);
                #pragma unroll
                for (int mt = 0; mt < 4; mt++) {
                    mma16816(acc[mt][ntp * 2],     af[mt][0], af[mt][1], af[mt][2], af[mt][3], b0, b1);
                    mma16816(acc[mt][ntp * 2 + 1], af[mt][0], af[mt][1], af[mt][2], af[mt][3], b2, b3);
                }
            }
        }
    }

    #pragma unroll
    for (int mt = 0; mt < 4; mt++) {
        int r0 = mBase + wm * 64 + mt * 16 + g;
        int r1 = r0 + 8;
        int b0i = r0 >> 11, l0 = r0 & 2047;
        int b1i = r1 >> 11, l1 = r1 & 2047;
        #pragma unroll
        for (int nt = 0; nt < 4; nt++) {
            int n = wn * 32 + nt * 8 + tq * 2;
            int head = h0 + (n >> 6), e = n & 63;
            __half* c0 = C + (((size_t)(head * BB + b0i) << 11) + l0) * DH;
            __half* c1 = C + (((size_t)(head * BB + b1i) << 11) + l1) * DH;
            *(unsigned*)&c0[e] = pack2(acc[mt][nt][0], acc[mt][nt][1]);
            *(unsigned*)&c1[e] = pack2(acc[mt][nt][2], acc[mt][nt][3]);
        }
    }
}

// ---------------------------------------------------------------------------
// Output projection: g_x = Ocat @ Wo + bo + resid (fp32 out)
// ---------------------------------------------------------------------------
__global__ __launch_bounds__(256, 2) void outproj_kernel(
    const float* __restrict__ resid, const float* __restrict__ bo)
{
    extern __shared__ __half dsm[];
    __half* Asm = dsm;
    __half* Bsm = dsm + 2 * ASZ;

    const int t = threadIdx.x;
    const int warp = t >> 5, lane = t & 31;
    const int g = lane >> 2, tq = lane & 3;
    const int wm = warp >> 2, wn = warp & 3;
    const int mBase = blockIdx.y * 128;
    const int nBase = blockIdx.x * 128;

    const int i8 = lane & 7, sel = lane >> 3;
    const int rowF = ((sel & 1) << 3) + i8;
    const int colF = (sel >> 1) << 3;
    const unsigned aSm = (unsigned)__cvta_generic_to_shared(Asm);
    const unsigned bSm = (unsigned)__cvta_generic_to_shared(Bsm);

    float acc[4][4][4];
    #pragma unroll
    for (int mt = 0; mt < 4; mt++)
        #pragma unroll
        for (int nt = 0; nt < 4; nt++)
            #pragma unroll
            for (int i = 0; i < 4; i++) acc[mt][nt][i] = 0.f;

    const int arow = t >> 3, aseg = (t & 7) * 8;
    const int brow = t >> 4, bseg = (t & 15) * 8;

    auto stage = [&](int kt, int buf) {
        const int kh = kt >> 6;
        #pragma unroll
        for (int it = 0; it < 4; it++) {
            int row = arow + it * 32;
            int m = mBase + row;
            int mb = m >> 11, ml = m & 2047;
            cp16(aSm + ((buf * 128 + row) * 72 + aseg) * 2,
                 &g_oh[(((size_t)(kh * BB + mb) << 11) + ml) * DH + aseg]);
        }
        #pragma unroll
        for (int it = 0; it < 4; it++) {
            int row = brow + it * 16;
            cp16(bSm + ((buf * 64 + row) * 136 + bseg) * 2,
                 &g_wo[(size_t)(kt + row) * DM + nBase + bseg]);
        }
        cp_commit();
    };

    stage(0, 0);
    const int NKT = DM / 64;
    for (int it = 0; it < NKT; it++) {
        cp_wait0();
        __syncthreads();
        if (it + 1 < NKT) stage((it + 1) * 64, (it + 1) & 1);
        const int abuf = (it & 1) * 128, bbuf = (it & 1) * 64;

        #pragma unroll
        for (int ks = 0; ks < 4; ks++) {
            unsigned af[4][4];
            #pragma unroll
            for (int mt = 0; mt < 4; mt++)
                ldsm4(af[mt][0], af[mt][1], af[mt][2], af[mt][3],
                      aSm + ((abuf + wm * 64 + mt * 16 + rowF) * 72 + ks * 16 + colF) * 2);
            #pragma unroll
            for (int ntp = 0; ntp < 2; ntp++) {
                unsigned b0, b1, b2, b3;
                ldsm4t(b0, b1, b2, b3,
                       bSm + ((bbuf + ks * 16 + rowF) * 136 + wn * 32 + ntp * 16 + colF) * 2);
                #pragma unroll
                for (int mt = 0; mt < 4; mt++) {
                    mma16816(acc[mt][ntp * 2],     af[mt][0], af[mt][1], af[mt][2], af[mt][3], b0, b1);
                    mma16816(acc[mt][ntp * 2 + 1], af[mt][0], af[mt][1], af[mt][2], af[mt][3], b2, b3);
                }
            }
        }
    }

    #pragma unroll
    for (int mt = 0; mt < 4; mt++) {
        int r0 = mBase + wm * 64 + mt * 16 + g;
        int r1 = r0 + 8;
        #pragma unroll
        for (int nt = 0; nt < 4; nt++) {
            int n = nBase + wn * 32 + nt * 8 + tq * 2;
            float2 bb = *(const float2*)&bo[n];
            float2 rA = *(const float2*)&resid[(size_t)r0 * DM + n];
            float2 rB = *(const float2*)&resid[(size_t)r1 * DM + n];
            *(float2*)&g_x[(size_t)r0 * DM + n] =
                make_float2(acc[mt][nt][0] + bb.x + rA.x, acc[mt][nt][1] + bb.y + rA.y);
            *(float2*)&g_x[(size_t)r1 * DM + n] =
                make_float2(acc[mt][nt][2] + bb.x + rB.x, acc[mt][nt][3] + bb.y + rB.y);
        }
    }
}

// ---------------------------------------------------------------------------
// Flash attention (fp16 mma, cp.async, f16x2 exp2 softmax, post-exp masking).
// ---------------------------------------------------------------------------
__global__ __launch_bounds__(256, 2) void attn_kernel()
{
    __shared__ __half Ks[2][64][72];
    __shared__ __half Vs[2][64][72];

    const int t = threadIdx.x;
    const int warp = t >> 5, lane = t & 31;
    const int g = lane >> 2, tq = lane & 3;
    const int hb = blockIdx.y;
    const int b = hb & 1;
    const int qBase = blockIdx.x * 128;

    const __half* __restrict__ Q = g_qh + (size_t)hb * SLQ * DH;
    const __half* __restrict__ K = g_kh + (size_t)hb * SLK * DH;
    const __half* __restrict__ V = g_vh + (size_t)hb * SLK * DH;
    __half* __restrict__ O = g_oh + (size_t)hb * SLQ * DH;

    const int r0 = qBase + warp * 16 + g;
    const int r1 = r0 + 8;

    unsigned qf[4][4];
    #pragma unroll
    for (int ks = 0; ks < 4; ks++) {
        qf[ks][0] = *(const unsigned*)&Q[(size_t)r0 * DH + ks * 16 + 2 * tq];
        qf[ks][1] = *(const unsigned*)&Q[(size_t)r1 * DH + ks * 16 + 2 * tq];
        qf[ks][2] = *(const unsigned*)&Q[(size_t)r0 * DH + ks * 16 + 8 + 2 * tq];
        qf[ks][3] = *(const unsigned*)&Q[(size_t)r1 * DH + ks * 16 + 8 + 2 * tq];
    }

    const int i8 = lane & 7, sel = lane >> 3;
    const int rowK = ((sel >> 1) << 3) + i8;
    const int colK = (sel & 1) << 3;
    const int rowV = ((sel & 1) << 3) + i8;
    const int colV = (sel >> 1) << 3;
    const unsigned kSm = (unsigned)__cvta_generic_to_shared(&Ks[0][0][0]);
    const unsigned vSm = (unsigned)__cvta_generic_to_shared(&Vs[0][0][0]);
    const unsigned kAddr0 = kSm + (rowK * 72 + colK) * 2;
    const unsigned vAddr0 = vSm + (rowV * 72 + colV) * 2;
    const unsigned BUFB = 64 * 72 * 2;

    float oc[8][4];
    #pragma unroll
    for (int dt = 0; dt < 8; dt++)
        #pragma unroll
        for (int i = 0; i < 4; i++) oc[dt][i] = 0.f;
    float m0 = -1e30f, m1 = -1e30f, l0 = 0.f, l1 = 0.f;

    const float c = 0.18033688011112042f;  // (1/8) * log2(e)
    const unsigned* mb0 = &g_mbits[((size_t)(b << 11) + r0) * 64];
    const unsigned* mb1 = &g_mbits[((size_t)(b << 11) + r1) * 64];
    const int tq2 = tq * 2;

    const int srow = t >> 3, sseg = (t & 7) * 8;

    auto stage = [&](int kb, int buf) {
        #pragma unroll
        for (int it = 0; it < 2; it++) {
            int row = srow + it * 32;
            cp16(kSm + ((buf * 64 + row) * 72 + sseg) * 2,
                 &K[(size_t)(kb + row) * DH + sseg]);
            cp16(vSm + ((buf * 64 + row) * 72 + sseg) * 2,
                 &V[(size_t)(kb + row) * DH + sseg]);
        }
        cp_commit();
    };

    stage(0, 0);
    const int NT = SLK / 64;
    for (int it = 0; it < NT; it++) {
        cp_wait0();
        __syncthreads();
        if (it + 1 < NT) stage((it + 1) * 64, (it + 1) & 1);
        const unsigned kA = kAddr0 + (it & 1) * BUFB;
        const unsigned vA = vAddr0 + (it & 1) * BUFB;
        const int kb = it * 64;

        // mask words: issue loads early so they complete under the S MMAs
        uint2 w0 = *(const uint2*)&mb0[kb >> 5];
        uint2 w1 = *(const uint2*)&mb1[kb >> 5];

        float sc[8][4];
        #pragma unroll
        for (int nt = 0; nt < 8; nt++)
            #pragma unroll
            for (int i = 0; i < 4; i++) sc[nt][i] = 0.f;

        #pragma unroll
        for (int ks = 0; ks < 4; ks++) {
            #pragma unroll
            for (int ntp = 0; ntp < 4; ntp++) {
                unsigned b0, b1, b2, b3;
                ldsm4(b0, b1, b2, b3, kA + (ntp * 16 * 72 + ks * 16) * 2);
                mma16816(sc[ntp * 2],     qf[ks][0], qf[ks][1], qf[ks][2], qf[ks][3], b0, b1);
                mma16816(sc[ntp * 2 + 1], qf[ks][0], qf[ks][1], qf[ks][2], qf[ks][3], b2, b3);
            }
        }

        // scale (unconditional) into log2 domain
        #pragma unroll
        for (int nt = 0; nt < 8; nt++) {
            sc[nt][0] *= c; sc[nt][1] *= c;
            sc[nt][2] *= c; sc[nt][3] *= c;
        }

        // row max over ALL scores (masked entries included — only a stabilizer)
        float mx0 = -1e30f, mx1 = -1e30f;
        #pragma unroll
        for (int nt = 0; nt < 8; nt++) {
            mx0 = fmaxf(mx0, fmaxf(sc[nt][0], sc[nt][1]));
            mx1 = fmaxf(mx1, fmaxf(sc[nt][2], sc[nt][3]));
        }
        mx0 = fmaxf(mx0, __shfl_xor_sync(0xffffffffu, mx0, 1));
        mx0 = fmaxf(mx0, __shfl_xor_sync(0xffffffffu, mx0, 2));
        mx1 = fmaxf(mx1, __shfl_xor_sync(0xffffffffu, mx1, 1));
        mx1 = fmaxf(mx1, __shfl_xor_sync(0xffffffffu, mx1, 2));

        float newm0 = fmaxf(m0, mx0), newm1 = fmaxf(m1, mx1);
        float al0 = ex2f(m0 - newm0), al1 = ex2f(m1 - newm1);
        m0 = newm0; m1 = newm1;

        // p = 2^(s-m) (f16x2), then zero masked entries with a half2 multiply
        unsigned long long mq0 =
            ((unsigned long long)w0.x | ((unsigned long long)w0.y << 32)) >> tq2;
        unsigned long long mq1 =
            ((unsigned long long)w1.x | ((unsigned long long)w1.y << 32)) >> tq2;

        unsigned pf[8][2];
        __half2 hs0 = __floats2half2_rn(0.f, 0.f);
        __half2 hs1 = hs0;
        #pragma unroll
        for (int nt = 0; nt < 8; nt++) {
            unsigned bb0 = (unsigned)(mq0 >> (nt * 8)) & 3u;
            unsigned bb1 = (unsigned)(mq1 >> (nt * 8)) & 3u;
            unsigned mm0v = 0x3C003C00u;
            if (bb0 & 1u) mm0v &= 0xFFFF0000u;
            if (bb0 & 2u) mm0v &= 0x0000FFFFu;
            unsigned mm1v = 0x3C003C00u;
            if (bb1 & 1u) mm1v &= 0xFFFF0000u;
            if (bb1 & 2u) mm1v &= 0x0000FFFFu;
            pf[nt][0] = hmul2(ex2h2(pack2(sc[nt][0] - newm0, sc[nt][1] - newm0)), mm0v);
            pf[nt][1] = hmul2(ex2h2(pack2(sc[nt][2] - newm1, sc[nt][3] - newm1)), mm1v);
            hs0 = __hadd2(hs0, *(__half2*)&pf[nt][0]);
            hs1 = __hadd2(hs1, *(__half2*)&pf[nt][1]);
        }
        float2 f0 = __half22float2(hs0);
        float2 f1 = __half22float2(hs1);
        float rs0 = f0.x + f0.y, rs1 = f1.x + f1.y;
        rs0 += __shfl_xor_sync(0xffffffffu, rs0, 1);
        rs0 += __shfl_xor_sync(0xffffffffu, rs0, 2);
        rs1 += __shfl_xor_sync(0xffffffffu, rs1, 1);
        rs1 += __shfl_xor_sync(0xffffffffu, rs1, 2);
        l0 = l0 * al0 + rs0;
        l1 = l1 * al1 + rs1;

        #pragma unroll
        for (int dt = 0; dt < 8; dt++) {
            oc[dt][0] *= al0; oc[dt][1] *= al0;
            oc[dt][2] *= al1; oc[dt][3] *= al1;
        }

        #pragma unroll
        for (int ks = 0; ks < 4; ks++) {
            unsigned a0 = pf[2 * ks][0], a1 = pf[2 * ks][1];
            unsigned a2 = pf[2 * ks + 1][0], a3 = pf[2 * ks + 1][1];
            #pragma unroll
            for (int dtp = 0; dtp < 4; dtp++) {
                unsigned b0, b1, b2, b3;
                ldsm4t(b0, b1, b2, b3, vA + (ks * 16 * 72 + dtp * 16) * 2);
                mma16816(oc[dtp * 2],     a0, a1, a2, a3, b0, b1);
                mma16816(oc[dtp * 2 + 1], a0, a1, a2, a3, b2, b3);
            }
        }
    }

    float inv0 = 1.f / l0, inv1 = 1.f / l1;
    #pragma unroll
    for (int dt = 0; dt < 8; dt++) {
        int d = dt * 8 + tq * 2;
        *(unsigned*)&O[(size_t)r0 * DH + d] = pack2(oc[dt][0] * inv0, oc[dt][1] * inv0);
        *(unsigned*)&O[(size_t)r1 * DH + d] = pack2(oc[dt][2] * inv1, oc[dt][3] * inv1);
    }
}

// ---------------------------------------------------------------------------
// LayerNorm (ddof=1, eps on std)
// ---------------------------------------------------------------------------
__global__ __launch_bounds__(256) void ln_kernel(
    const float* __restrict__ gamma, const float* __restrict__ beta,
    float* __restrict__ out)
{
    __shared__ float red[8];
    const int row = blockIdx.x;
    const int t = threadIdx.x;
    const float* x = g_x + (size_t)row * DM;

    float4 v = *(const float4*)&x[t * 4];
    float s = v.x + v.y + v.z + v.w;
    #pragma unroll
    for (int sft = 16; sft >= 1; sft >>= 1)
        s += __shfl_xor_sync(0xffffffffu, s, sft);
    if ((t & 31) == 0) red[t >> 5] = s;
    __syncthreads();
    float tot = 0.f;
    #pragma unroll
    for (int w = 0; w < 8; w++) tot += red[w];
    float mean = tot * (1.0f / DM);
    __syncthreads();

    float d0 = v.x - mean, d1 = v.y - mean, d2 = v.z - mean, d3 = v.w - mean;
    float sq = d0 * d0 + d1 * d1 + d2 * d2 + d3 * d3;
    #pragma unroll
    for (int sft = 16; sft >= 1; sft >>= 1)
        sq += __shfl_xor_sync(0xffffffffu, sq, sft);
    if ((t & 31) == 0) red[t >> 5] = sq;
    __syncthreads();
    float sqt = 0.f;
    #pragma unroll
    for (int w = 0; w < 8; w++) sqt += red[w];
    float stdv = sqrtf(sqt * (1.0f / (DM - 1)));
    float inv = 1.0f / (stdv + 1e-3f);

    float4 gm = *(const float4*)&gamma[t * 4];
    float4 be = *(const float4*)&beta[t * 4];
    float4 o;
    o.x = d0 * inv * gm.x + be.x;
    o.y = d1 * inv * gm.y + be.y;
    o.z = d2 * inv * gm.z + be.z;
    o.w = d3 * inv * gm.w + be.w;
    *(float4*)&out[(size_t)row * DM + t * 4] = o;
}

// ---------------------------------------------------------------------------
extern "C" void kernel_launch(void* const* d_in, const int* in_sizes, int n_in,
                              void* d_out, int out_size)
{
    const float* v_in  = (const float*)d_in[0];
    const float* k_in  = (const float*)d_in[1];
    const float* q_in  = (const float*)d_in[2];
    const void*  mask  = d_in[3];
    const float* w_q   = (const float*)d_in[4];
    const float* w_k   = (const float*)d_in[5];
    const float* w_v   = (const float*)d_in[6];
    const float* w_o   = (const float*)d_in[7];
    const float* b_o   = (const float*)d_in[8];
    const float* gamma = (const float*)d_in[9];
    const float* beta  = (const float*)d_in[10];
    float* out = (float*)d_out;

    cudaFuncSetAttribute(proj_kernel, cudaFuncAttributeMaxDynamicSharedMemorySize, GEMM_SMEM);
    cudaFuncSetAttribute(outproj_kernel, cudaFuncAttributeMaxDynamicSharedMemorySize, GEMM_SMEM);

    prep_kernel<<<dim3(384, 8), 256>>>(q_in, k_in, v_in, w_q, w_k, w_v, w_o, mask);

    proj_kernel<<<dim3(NH / 2, MROWS / 128, 3), 256, GEMM_SMEM>>>();
    attn_kernel<<<dim3(SLQ / 128, NH * BB), 256>>>();
    outproj_kernel<<<dim3(DM / 128, MROWS / 128), 256, GEMM_SMEM>>>(k_in, b_o);
    ln_kernel<<<MROWS, 256>>>(gamma, beta, out);
}

// round 14
// speedup vs baseline: 1.0128x; 1.0128x over previous
#include <cuda_runtime.h>
#include <cuda_fp16.h>
#include <cstdint>

#define BB 2
#define SLQ 2048
#define SLK 2048
#define DM 1024
#define NH 16
#define DH 64
#define MROWS (BB*SLQ)   // 4096

// Scratch (allocation-free rule: device globals)
__device__ __half g_qh[NH*BB*SLQ*DH];
__device__ __half g_kh[NH*BB*SLK*DH];
__device__ __half g_vh[NH*BB*SLK*DH];
__device__ __half g_oh[NH*BB*SLQ*DH];
__device__ __half g_xq[MROWS*DM];
__device__ __half g_xk[MROWS*DM];
__device__ __half g_xv[MROWS*DM];
__device__ __half g_wq[NH*DM*DH];
__device__ __half g_wk[NH*DM*DH];
__device__ __half g_wv[NH*DM*DH];
__device__ __half g_wo[DM*DM];
__device__ float  g_x [MROWS*DM];
__device__ unsigned int g_mbits[BB*SLQ*(SLK/32)];

// ---------------------------------------------------------------------------
__device__ __forceinline__ unsigned pack2(float a, float b) {
    __half2 h = __floats2half2_rn(a, b);
    return *(unsigned*)&h;
}

__device__ __forceinline__ unsigned ex2h2(unsigned x) {
    unsigned r;
    asm("ex2.approx.f16x2 %0, %1;" : "=r"(r) : "r"(x));
    return r;
}

__device__ __forceinline__ unsigned hmul2(unsigned a, unsigned b) {
    unsigned r;
    asm("mul.f16x2 %0, %1, %2;" : "=r"(r) : "r"(a), "r"(b));
    return r;
}

__device__ __forceinline__ float ex2f(float x) {
    float r;
    asm("ex2.approx.f32 %0, %1;" : "=f"(r) : "f"(x));
    return r;
}

__device__ __forceinline__ void mma16816(float* c,
    unsigned a0, unsigned a1, unsigned a2, unsigned a3,
    unsigned b0, unsigned b1)
{
    asm volatile(
        "mma.sync.aligned.m16n8k16.row.col.f32.f16.f16.f32 "
        "{%0,%1,%2,%3}, {%4,%5,%6,%7}, {%8,%9}, {%0,%1,%2,%3};"
        : "+f"(c[0]), "+f"(c[1]), "+f"(c[2]), "+f"(c[3])
        : "r"(a0), "r"(a1), "r"(a2), "r"(a3), "r"(b0), "r"(b1));
}

__device__ __forceinline__ void ldsm4(unsigned& r0, unsigned& r1,
                                      unsigned& r2, unsigned& r3, unsigned addr)
{
    asm volatile("ldmatrix.sync.aligned.m8n8.x4.shared.b16 {%0,%1,%2,%3}, [%4];"
        : "=r"(r0), "=r"(r1), "=r"(r2), "=r"(r3) : "r"(addr));
}

__device__ __forceinline__ void ldsm4t(unsigned& r0, unsigned& r1,
                                       unsigned& r2, unsigned& r3, unsigned addr)
{
    asm volatile("ldmatrix.sync.aligned.m8n8.x4.trans.shared.b16 {%0,%1,%2,%3}, [%4];"
        : "=r"(r0), "=r"(r1), "=r"(r2), "=r"(r3) : "r"(addr));
}

__device__ __forceinline__ void cp16(unsigned smem, const void* gptr)
{
    asm volatile("cp.async.cg.shared.global [%0], [%1], 16;" :: "r"(smem), "l"(gptr));
}
__device__ __forceinline__ void cp_commit() { asm volatile("cp.async.commit_group;"); }
__device__ __forceinline__ void cp_wait0()  { asm volatile("cp.async.wait_group 0;"); }

// ---------------------------------------------------------------------------
// Fused prep: regions 0-6 fp32->fp16 conversion; region 7 packs the mask into
// bits (bit=1 -> masked). Mask dtype sniffed per-block.
// ---------------------------------------------------------------------------
__global__ void prep_kernel(
    const float* __restrict__ s0, const float* __restrict__ s1,
    const float* __restrict__ s2, const float* __restrict__ s3,
    const float* __restrict__ s4, const float* __restrict__ s5,
    const float* __restrict__ s6, const void* __restrict__ mraw)
{
    if (blockIdx.y == 7) {
        __shared__ int s_u8;
        const int lane = threadIdx.x & 31;
        if (threadIdx.x == 0) s_u8 = 0;
        __syncthreads();
        {
            const unsigned int* mw = (const unsigned int*)mraw;
            int found = 0;
            for (int i = threadIdx.x; i < 16384; i += blockDim.x)
                if (mw[i] > 1u) { found = 1; break; }
            if (found) s_u8 = 1;
        }
        __syncthreads();
        const bool u8 = (s_u8 != 0);

        const int nwords = BB * SLQ * (SLK / 32);  // 262144 output words
        int gw = (blockIdx.x * blockDim.x + threadIdx.x) >> 5;
        const int stride = (gridDim.x * blockDim.x) >> 5;
        if (!u8) {
            // vectorized: each warp-chunk reads 128 int32 elements -> 4 words.
            // total chunks = nwords / 4   (BUG FIX: was /4/32)
            const int nchunks = nwords / 4;        // 65536
            for (int ch = gw; ch < nchunks; ch += stride) {
                int4 v = ((const int4*)mraw)[ch * 32 + lane];
                unsigned nib = (v.x ? 1u : 0u) | (v.y ? 2u : 0u)
                             | (v.z ? 4u : 0u) | (v.w ? 8u : 0u);
                unsigned acc = nib << ((lane & 7) * 4);
                acc |= __shfl_xor_sync(0xffffffffu, acc, 1);
                acc |= __shfl_xor_sync(0xffffffffu, acc, 2);
                acc |= __shfl_xor_sync(0xffffffffu, acc, 4);
                if ((lane & 7) == 0) g_mbits[ch * 4 + (lane >> 3)] = acc;
            }
        } else {
            for (int w = gw; w < nwords; w += stride) {
                int idx = w * 32 + lane;
                int v = (int)((const unsigned char*)mraw)[idx];
                unsigned int bits = __ballot_sync(0xffffffffu, v != 0);
                if (lane == 0) g_mbits[w] = bits;
            }
        }
        return;
    }

    const float* src;
    __half* dst;
    int n;
    switch (blockIdx.y) {
        case 0: src = s0; dst = g_xq; n = MROWS * DM; break;
        case 1: src = s1; dst = g_xk; n = MROWS * DM; break;
        case 2: src = s2; dst = g_xv; n = MROWS * DM; break;
        case 3: src = s3; dst = g_wq; n = NH * DM * DH; break;
        case 4: src = s4; dst = g_wk; n = NH * DM * DH; break;
        case 5: src = s5; dst = g_wv; n = NH * DM * DH; break;
        default: src = s6; dst = g_wo; n = DM * DM; break;
    }
    int i = (blockIdx.x * blockDim.x + threadIdx.x) * 4;
    int stride = gridDim.x * blockDim.x * 4;
    for (; i < n; i += stride) {
        float4 v = *(const float4*)&src[i];
        *(uint2*)&dst[i] = make_uint2(pack2(v.x, v.y), pack2(v.z, v.w));
    }
}

// ---------------------------------------------------------------------------
// Projection GEMM (fp16 mma): C[h,b,l,e] = sum_d X[b,l,d]*W[h,d,e]
// ---------------------------------------------------------------------------
#define ASZ (128*72)
#define BSZ (64*136)
#define GEMM_SMEM ((2*ASZ + 2*BSZ) * 2)

__global__ __launch_bounds__(256, 2) void proj_kernel()
{
    extern __shared__ __half dsm[];
    __half* Asm = dsm;
    __half* Bsm = dsm + 2 * ASZ;

    const __half* __restrict__ X;
    const __half* __restrict__ W;
    __half* __restrict__ C;
    if (blockIdx.z == 0)      { X = g_xq; W = g_wq; C = g_qh; }
    else if (blockIdx.z == 1) { X = g_xk; W = g_wk; C = g_kh; }
    else                      { X = g_xv; W = g_wv; C = g_vh; }

    const int t = threadIdx.x;
    const int warp = t >> 5, lane = t & 31;
    const int g = lane >> 2, tq = lane & 3;
    const int wm = warp >> 2, wn = warp & 3;
    const int mBase = blockIdx.y * 128;
    const int h0 = blockIdx.x * 2;

    const int i8 = lane & 7, sel = lane >> 3;
    const int rowF = ((sel & 1) << 3) + i8;
    const int colF = (sel >> 1) << 3;
    const unsigned aSm = (unsigned)__cvta_generic_to_shared(Asm);
    const unsigned bSm = (unsigned)__cvta_generic_to_shared(Bsm);

    float acc[4][4][4];
    #pragma unroll
    for (int mt = 0; mt < 4; mt++)
        #pragma unroll
        for (int nt = 0; nt < 4; nt++)
            #pragma unroll
            for (int i = 0; i < 4; i++) acc[mt][nt][i] = 0.f;

    const int arow = t >> 3, aseg = (t & 7) * 8;
    const int brow = t >> 4, bseg = (t & 15) * 8;

    auto stage = [&](int kt, int buf) {
        #pragma unroll
        for (int it = 0; it < 4; it++) {
            int row = arow + it * 32;
            cp16(aSm + ((buf * 128 + row) * 72 + aseg) * 2,
                 &X[(size_t)(mBase + row) * DM + kt + aseg]);
        }
        #pragma unroll
        for (int it = 0; it < 4; it++) {
            int row = brow + it * 16;
            int head = h0 + (bseg >> 6), e = bseg & 63;
            cp16(bSm + ((buf * 64 + row) * 136 + bseg) * 2,
                 &W[((size_t)head * DM + kt + row) * DH + e]);
        }
        cp_commit();
    };

    stage(0, 0);
    const int NKT = DM / 64;  // 16
    for (int it = 0; it < NKT; it++) {
        cp_wait0();
        __syncthreads();
        if (it + 1 < NKT) stage((it + 1) * 64, (it + 1) & 1);
        const int abuf = (it & 1) * 128, bbuf = (it & 1) * 64;

        #pragma unroll
        for (int ks = 0; ks < 4; ks++) {
            unsigned af[4][4];
            #pragma unroll
            for (int mt = 0; mt < 4; mt++)
                ldsm4(af[mt][0], af[mt][1], af[mt][2], af[mt][3],
                      aSm + ((abuf + wm * 64 + mt * 16 + rowF) * 72 + ks * 16 + colF) * 2);
            #pragma unroll
            for (int ntp = 0; ntp < 2; ntp++) {
                unsigned b0, b1, b2, b3;
                ldsm4t(b0, b1, b2, b3,
                       bSm + ((bbuf + ks * 16 + rowF) * 136 + wn * 32 + ntp * 16 + colF) * 2);
                #pragma unroll
                for (int mt = 0; mt < 4; mt++) {
                    mma16816(acc[mt][ntp * 2],     af[mt][0], af[mt][1], af[mt][2], af[mt][3], b0, b1);
                    mma16816(acc[mt][ntp * 2 + 1], af[mt][0], af[mt][1], af[mt][2], af[mt][3], b2, b3);
                }
            }
        }
    }

    #pragma unroll
    for (int mt = 0; mt < 4; mt++) {
        int r0 = mBase + wm * 64 + mt * 16 + g;
        int r1 = r0 + 8;
        int b0i = r0 >> 11, l0 = r0 & 2047;
        int b1i = r1 >> 11, l1 = r1 & 2047;
        #pragma unroll
        for (int nt = 0; nt < 4; nt++) {
            int n = wn * 32 + nt * 8 + tq * 2;
            int head = h0 + (n >> 6), e = n & 63;
            __half* c0 = C + (((size_t)(head * BB + b0i) << 11) + l0) * DH;
            __half* c1 = C + (((size_t)(head * BB + b1i) << 11) + l1) * DH;
            *(unsigned*)&c0[e] = pack2(acc[mt][nt][0], acc[mt][nt][1]);
            *(unsigned*)&c1[e] = pack2(acc[mt][nt][2], acc[mt][nt][3]);
        }
    }
}

// ---------------------------------------------------------------------------
// Output projection: g_x = Ocat @ Wo + bo + resid (fp32 out)
// ---------------------------------------------------------------------------
__global__ __launch_bounds__(256, 2) void outproj_kernel(
    const float* __restrict__ resid, const float* __restrict__ bo)
{
    extern __shared__ __half dsm[];
    __half* Asm = dsm;
    __half* Bsm = dsm + 2 * ASZ;

    const int t = threadIdx.x;
    const int warp = t >> 5, lane = t & 31;
    const int g = lane >> 2, tq = lane & 3;
    const int wm = warp >> 2, wn = warp & 3;
    const int mBase = blockIdx.y * 128;
    const int nBase = blockIdx.x * 128;

    const int i8 = lane & 7, sel = lane >> 3;
    const int rowF = ((sel & 1) << 3) + i8;
    const int colF = (sel >> 1) << 3;
    const unsigned aSm = (unsigned)__cvta_generic_to_shared(Asm);
    const unsigned bSm = (unsigned)__cvta_generic_to_shared(Bsm);

    float acc[4][4][4];
    #pragma unroll
    for (int mt = 0; mt < 4; mt++)
        #pragma unroll
        for (int nt = 0; nt < 4; nt++)
            #pragma unroll
            for (int i = 0; i < 4; i++) acc[mt][nt][i] = 0.f;

    const int arow = t >> 3, aseg = (t & 7) * 8;
    const int brow = t >> 4, bseg = (t & 15) * 8;

    auto stage = [&](int kt, int buf) {
        const int kh = kt >> 6;
        #pragma unroll
        for (int it = 0; it < 4; it++) {
            int row = arow + it * 32;
            int m = mBase + row;
            int mb = m >> 11, ml = m & 2047;
            cp16(aSm + ((buf * 128 + row) * 72 + aseg) * 2,
                 &g_oh[(((size_t)(kh * BB + mb) << 11) + ml) * DH + aseg]);
        }
        #pragma unroll
        for (int it = 0; it < 4; it++) {
            int row = brow + it * 16;
            cp16(bSm + ((buf * 64 + row) * 136 + bseg) * 2,
                 &g_wo[(size_t)(kt + row) * DM + nBase + bseg]);
        }
        cp_commit();
    };

    stage(0, 0);
    const int NKT = DM / 64;
    for (int it = 0; it < NKT; it++) {
        cp_wait0();
        __syncthreads();
        if (it + 1 < NKT) stage((it + 1) * 64, (it + 1) & 1);
        const int abuf = (it & 1) * 128, bbuf = (it & 1) * 64;

        #pragma unroll
        for (int ks = 0; ks < 4; ks++) {
            unsigned af[4][4];
            #pragma unroll
            for (int mt = 0; mt < 4; mt++)
                ldsm4(af[mt][0], af[mt][1], af[mt][2], af[mt][3],
                      aSm + ((abuf + wm * 64 + mt * 16 + rowF) * 72 + ks * 16 + colF) * 2);
            #pragma unroll
            for (int ntp = 0; ntp < 2; ntp++) {
                unsigned b0, b1, b2, b3;
                ldsm4t(b0, b1, b2, b3,
                       bSm + ((bbuf + ks * 16 + rowF) * 136 + wn * 32 + ntp * 16 + colF) * 2);
                #pragma unroll
                for (int mt = 0; mt < 4; mt++) {
                    mma16816(acc[mt][ntp * 2],     af[mt][0], af[mt][1], af[mt][2], af[mt][3], b0, b1);
                    mma16816(acc[mt][ntp * 2 + 1], af[mt][0], af[mt][1], af[mt][2], af[mt][3], b2, b3);
                }
            }
        }
    }

    #pragma unroll
    for (int mt = 0; mt < 4; mt++) {
        int r0 = mBase + wm * 64 + mt * 16 + g;
        int r1 = r0 + 8;
        #pragma unroll
        for (int nt = 0; nt < 4; nt++) {
            int n = nBase + wn * 32 + nt * 8 + tq * 2;
            float2 bb = *(const float2*)&bo[n];
            float2 rA = *(const float2*)&resid[(size_t)r0 * DM + n];
            float2 rB = *(const float2*)&resid[(size_t)r1 * DM + n];
            *(float2*)&g_x[(size_t)r0 * DM + n] =
                make_float2(acc[mt][nt][0] + bb.x + rA.x, acc[mt][nt][1] + bb.y + rA.y);
            *(float2*)&g_x[(size_t)r1 * DM + n] =
                make_float2(acc[mt][nt][2] + bb.x + rB.x, acc[mt][nt][3] + bb.y + rB.y);
        }
    }
}

// ---------------------------------------------------------------------------
// Flash attention (fp16 mma, cp.async, f16x2 exp2 softmax, post-exp masking).
// Scale folded into Q fragments; alpha-rescale skipped when warp-uniformly
// no row max changed.
// ---------------------------------------------------------------------------
__global__ __launch_bounds__(256, 2) void attn_kernel()
{
    __shared__ __half Ks[2][64][72];
    __shared__ __half Vs[2][64][72];

    const int t = threadIdx.x;
    const int warp = t >> 5, lane = t & 31;
    const int g = lane >> 2, tq = lane & 3;
    const int hb = blockIdx.y;
    const int b = hb & 1;
    const int qBase = blockIdx.x * 128;

    const __half* __restrict__ Q = g_qh + (size_t)hb * SLQ * DH;
    const __half* __restrict__ K = g_kh + (size_t)hb * SLK * DH;
    const __half* __restrict__ V = g_vh + (size_t)hb * SLK * DH;
    __half* __restrict__ O = g_oh + (size_t)hb * SLQ * DH;

    const int r0 = qBase + warp * 16 + g;
    const int r1 = r0 + 8;

    // Q fragments, pre-scaled by c = (1/8)*log2(e) (log2-domain softmax)
    const unsigned ch2 = 0x31C531C5u;   // half2(0.1803...)
    unsigned qf[4][4];
    #pragma unroll
    for (int ks = 0; ks < 4; ks++) {
        qf[ks][0] = hmul2(*(const unsigned*)&Q[(size_t)r0 * DH + ks * 16 + 2 * tq], ch2);
        qf[ks][1] = hmul2(*(const unsigned*)&Q[(size_t)r1 * DH + ks * 16 + 2 * tq], ch2);
        qf[ks][2] = hmul2(*(const unsigned*)&Q[(size_t)r0 * DH + ks * 16 + 8 + 2 * tq], ch2);
        qf[ks][3] = hmul2(*(const unsigned*)&Q[(size_t)r1 * DH + ks * 16 + 8 + 2 * tq], ch2);
    }

    const int i8 = lane & 7, sel = lane >> 3;
    const int rowK = ((sel >> 1) << 3) + i8;
    const int colK = (sel & 1) << 3;
    const int rowV = ((sel & 1) << 3) + i8;
    const int colV = (sel >> 1) << 3;
    const unsigned kSm = (unsigned)__cvta_generic_to_shared(&Ks[0][0][0]);
    const unsigned vSm = (unsigned)__cvta_generic_to_shared(&Vs[0][0][0]);
    const unsigned kAddr0 = kSm + (rowK * 72 + colK) * 2;
    const unsigned vAddr0 = vSm + (rowV * 72 + colV) * 2;
    const unsigned BUFB = 64 * 72 * 2;

    float oc[8][4];
    #pragma unroll
    for (int dt = 0; dt < 8; dt++)
        #pragma unroll
        for (int i = 0; i < 4; i++) oc[dt][i] = 0.f;
    float m0 = -1e30f, m1 = -1e30f, l0 = 0.f, l1 = 0.f;

    const unsigned* mb0 = &g_mbits[((size_t)(b << 11) + r0) * 64];
    const unsigned* mb1 = &g_mbits[((size_t)(b << 11) + r1) * 64];
    const int tq2 = tq * 2;

    const int srow = t >> 3, sseg = (t & 7) * 8;

    auto stage = [&](int kb, int buf) {
        #pragma unroll
        for (int it = 0; it < 2; it++) {
            int row = srow + it * 32;
            cp16(kSm + ((buf * 64 + row) * 72 + sseg) * 2,
                 &K[(size_t)(kb + row) * DH + sseg]);
            cp16(vSm + ((buf * 64 + row) * 72 + sseg) * 2,
                 &V[(size_t)(kb + row) * DH + sseg]);
        }
        cp_commit();
    };

    stage(0, 0);
    const int NT = SLK / 64;
    for (int it = 0; it < NT; it++) {
        cp_wait0();
        __syncthreads();
        if (it + 1 < NT) stage((it + 1) * 64, (it + 1) & 1);
        const unsigned kA = kAddr0 + (it & 1) * BUFB;
        const unsigned vA = vAddr0 + (it & 1) * BUFB;
        const int kb = it * 64;

        // mask words: issue early so loads complete under S MMAs
        uint2 w0 = *(const uint2*)&mb0[kb >> 5];
        uint2 w1 = *(const uint2*)&mb1[kb >> 5];

        float sc[8][4];
        #pragma unroll
        for (int nt = 0; nt < 8; nt++)
            #pragma unroll
            for (int i = 0; i < 4; i++) sc[nt][i] = 0.f;

        #pragma unroll
        for (int ks = 0; ks < 4; ks++) {
            #pragma unroll
            for (int ntp = 0; ntp < 4; ntp++) {
                unsigned b0, b1, b2, b3;
                ldsm4(b0, b1, b2, b3, kA + (ntp * 16 * 72 + ks * 16) * 2);
                mma16816(sc[ntp * 2],     qf[ks][0], qf[ks][1], qf[ks][2], qf[ks][3], b0, b1);
                mma16816(sc[ntp * 2 + 1], qf[ks][0], qf[ks][1], qf[ks][2], qf[ks][3], b2, b3);
            }
        }

        // row max over ALL (already log2-scaled) scores
        float mx0 = -1e30f, mx1 = -1e30f;
        #pragma unroll
        for (int nt = 0; nt < 8; nt++) {
            mx0 = fmaxf(mx0, fmaxf(sc[nt][0], sc[nt][1]));
            mx1 = fmaxf(mx1, fmaxf(sc[nt][2], sc[nt][3]));
        }
        mx0 = fmaxf(mx0, __shfl_xor_sync(0xffffffffu, mx0, 1));
        mx0 = fmaxf(mx0, __shfl_xor_sync(0xffffffffu, mx0, 2));
        mx1 = fmaxf(mx1, __shfl_xor_sync(0xffffffffu, mx1, 1));
        mx1 = fmaxf(mx1, __shfl_xor_sync(0xffffffffu, mx1, 2));

        float newm0 = fmaxf(m0, mx0), newm1 = fmaxf(m1, mx1);
        bool nochg = (newm0 == m0) && (newm1 == m1);
        bool allno = __all_sync(0xffffffffu, nochg);
        float al0 = 1.f, al1 = 1.f;
        if (!allno) {
            al0 = ex2f(m0 - newm0);
            al1 = ex2f(m1 - newm1);
            m0 = newm0; m1 = newm1;
        }

        // p = 2^(s-m) (f16x2), zero masked entries with a half2 multiply
        unsigned long long mq0 =
            ((unsigned long long)w0.x | ((unsigned long long)w0.y << 32)) >> tq2;
        unsigned long long mq1 =
            ((unsigned long long)w1.x | ((unsigned long long)w1.y << 32)) >> tq2;

        unsigned pf[8][2];
        __half2 hs0 = __floats2half2_rn(0.f, 0.f);
        __half2 hs1 = hs0;
        #pragma unroll
        for (int nt = 0; nt < 8; nt++) {
            unsigned bb0 = (unsigned)(mq0 >> (nt * 8)) & 3u;
            unsigned bb1 = (unsigned)(mq1 >> (nt * 8)) & 3u;
            unsigned mm0v = 0x3C003C00u;
            if (bb0 & 1u) mm0v &= 0xFFFF0000u;
            if (bb0 & 2u) mm0v &= 0x0000FFFFu;
            unsigned mm1v = 0x3C003C00u;
            if (bb1 & 1u) mm1v &= 0xFFFF0000u;
            if (bb1 & 2u) mm1v &= 0x0000FFFFu;
            pf[nt][0] = hmul2(ex2h2(pack2(sc[nt][0] - newm0, sc[nt][1] - newm0)), mm0v);
            pf[nt][1] = hmul2(ex2h2(pack2(sc[nt][2] - newm1, sc[nt][3] - newm1)), mm1v);
            hs0 = __hadd2(hs0, *(__half2*)&pf[nt][0]);
            hs1 = __hadd2(hs1, *(__half2*)&pf[nt][1]);
        }
        float2 f0 = __half22float2(hs0);
        float2 f1 = __half22float2(hs1);
        float rs0 = f0.x + f0.y, rs1 = f1.x + f1.y;
        rs0 += __shfl_xor_sync(0xffffffffu, rs0, 1);
        rs0 += __shfl_xor_sync(0xffffffffu, rs0, 2);
        rs1 += __shfl_xor_sync(0xffffffffu, rs1, 1);
        rs1 += __shfl_xor_sync(0xffffffffu, rs1, 2);
        l0 = l0 * al0 + rs0;
        l1 = l1 * al1 + rs1;

        if (!allno) {
            #pragma unroll
            for (int dt = 0; dt < 8; dt++) {
                oc[dt][0] *= al0; oc[dt][1] *= al0;
                oc[dt][2] *= al1; oc[dt][3] *= al1;
            }
        }

        #pragma unroll
        for (int ks = 0; ks < 4; ks++) {
            unsigned a0 = pf[2 * ks][0], a1 = pf[2 * ks][1];
            unsigned a2 = pf[2 * ks + 1][0], a3 = pf[2 * ks + 1][1];
            #pragma unroll
            for (int dtp = 0; dtp < 4; dtp++) {
                unsigned b0, b1, b2, b3;
                ldsm4t(b0, b1, b2, b3, vA + (ks * 16 * 72 + dtp * 16) * 2);
                mma16816(oc[dtp * 2],     a0, a1, a2, a3, b0, b1);
                mma16816(oc[dtp * 2 + 1], a0, a1, a2, a3, b2, b3);
            }
        }
    }

    float inv0 = 1.f / l0, inv1 = 1.f / l1;
    #pragma unroll
    for (int dt = 0; dt < 8; dt++) {
        int d = dt * 8 + tq * 2;
        *(unsigned*)&O[(size_t)r0 * DH + d] = pack2(oc[dt][0] * inv0, oc[dt][1] * inv0);
        *(unsigned*)&O[(size_t)r1 * DH + d] = pack2(oc[dt][2] * inv1, oc[dt][3] * inv1);
    }
}

// ---------------------------------------------------------------------------
// LayerNorm (ddof=1, eps on std)
// ---------------------------------------------------------------------------
__global__ __launch_bounds__(256) void ln_kernel(
    const float* __restrict__ gamma, const float* __restrict__ beta,
    float* __restrict__ out)
{
    __shared__ float red[8];
    const int row = blockIdx.x;
    const int t = threadIdx.x;
    const float* x = g_x + (size_t)row * DM;

    float4 v = *(const float4*)&x[t * 4];
    float s = v.x + v.y + v.z + v.w;
    #pragma unroll
    for (int sft = 16; sft >= 1; sft >>= 1)
        s += __shfl_xor_sync(0xffffffffu, s, sft);
    if ((t & 31) == 0) red[t >> 5] = s;
    __syncthreads();
    float tot = 0.f;
    #pragma unroll
    for (int w = 0; w < 8; w++) tot += red[w];
    float mean = tot * (1.0f / DM);
    __syncthreads();

    float d0 = v.x - mean, d1 = v.y - mean, d2 = v.z - mean, d3 = v.w - mean;
    float sq = d0 * d0 + d1 * d1 + d2 * d2 + d3 * d3;
    #pragma unroll
    for (int sft = 16; sft >= 1; sft >>= 1)
        sq += __shfl_xor_sync(0xffffffffu, sq, sft);
    if ((t & 31) == 0) red[t >> 5] = sq;
    __syncthreads();
    float sqt = 0.f;
    #pragma unroll
    for (int w = 0; w < 8; w++) sqt += red[w];
    float stdv = sqrtf(sqt * (1.0f / (DM - 1)));
    float inv = 1.0f / (stdv + 1e-3f);

    float4 gm = *(const float4*)&gamma[t * 4];
    float4 be = *(const float4*)&beta[t * 4];
    float4 o;
    o.x = d0 * inv * gm.x + be.x;
    o.y = d1 * inv * gm.y + be.y;
    o.z = d2 * inv * gm.z + be.z;
    o.w = d3 * inv * gm.w + be.w;
    *(float4*)&out[(size_t)row * DM + t * 4] = o;
}

// ---------------------------------------------------------------------------
extern "C" void kernel_launch(void* const* d_in, const int* in_sizes, int n_in,
                              void* d_out, int out_size)
{
    const float* v_in  = (const float*)d_in[0];
    const float* k_in  = (const float*)d_in[1];
    const float* q_in  = (const float*)d_in[2];
    const void*  mask  = d_in[3];
    const float* w_q   = (const float*)d_in[4];
    const float* w_k   = (const float*)d_in[5];
    const float* w_v   = (const float*)d_in[6];
    const float* w_o   = (const float*)d_in[7];
    const float* b_o   = (const float*)d_in[8];
    const float* gamma = (const float*)d_in[9];
    const float* beta  = (const float*)d_in[10];
    float* out = (float*)d_out;

    cudaFuncSetAttribute(proj_kernel, cudaFuncAttributeMaxDynamicSharedMemorySize, GEMM_SMEM);
    cudaFuncSetAttribute(outproj_kernel, cudaFuncAttributeMaxDynamicSharedMemorySize, GEMM_SMEM);

    prep_kernel<<<dim3(384, 8), 256>>>(q_in, k_in, v_in, w_q, w_k, w_v, w_o, mask);

    proj_kernel<<<dim3(NH / 2, MROWS / 128, 3), 256, GEMM_SMEM>>>();
    attn_kernel<<<dim3(SLQ / 128, NH * BB), 256>>>();
    outproj_kernel<<<dim3(DM / 128, MROWS / 128), 256, GEMM_SMEM>>>(k_in, b_o);
    ln_kernel<<<MROWS, 256>>>(gamma, beta, out);
}

// round 15
// speedup vs baseline: 1.0385x; 1.0254x over previous
#include <cuda_runtime.h>
#include <cuda_fp16.h>
#include <cstdint>

#define BB 2
#define SLQ 2048
#define SLK 2048
#define DM 1024
#define NH 16
#define DH 64
#define MROWS (BB*SLQ)   // 4096

// Scratch (allocation-free rule: device globals)
__device__ __half g_qh[NH*BB*SLQ*DH];
__device__ __half g_kh[NH*BB*SLK*DH];
__device__ __half g_vh[NH*BB*SLK*DH];
__device__ __half g_oh[NH*BB*SLQ*DH];
__device__ __half g_xq[MROWS*DM];
__device__ __half g_xk[MROWS*DM];
__device__ __half g_xv[MROWS*DM];
__device__ __half g_wq[NH*DM*DH];
__device__ __half g_wk[NH*DM*DH];
__device__ __half g_wv[NH*DM*DH];
__device__ __half g_wo[DM*DM];
__device__ float  g_x [MROWS*DM];
__device__ unsigned int g_mbits[BB*SLQ*(SLK/32)];

// ---------------------------------------------------------------------------
__device__ __forceinline__ unsigned pack2(float a, float b) {
    __half2 h = __floats2half2_rn(a, b);
    return *(unsigned*)&h;
}

__device__ __forceinline__ unsigned ex2h2(unsigned x) {
    unsigned r;
    asm("ex2.approx.f16x2 %0, %1;" : "=r"(r) : "r"(x));
    return r;
}

__device__ __forceinline__ unsigned hmul2(unsigned a, unsigned b) {
    unsigned r;
    asm("mul.f16x2 %0, %1, %2;" : "=r"(r) : "r"(a), "r"(b));
    return r;
}

__device__ __forceinline__ float ex2f(float x) {
    float r;
    asm("ex2.approx.f32 %0, %1;" : "=f"(r) : "f"(x));
    return r;
}

__device__ __forceinline__ void mma16816(float* c,
    unsigned a0, unsigned a1, unsigned a2, unsigned a3,
    unsigned b0, unsigned b1)
{
    asm volatile(
        "mma.sync.aligned.m16n8k16.row.col.f32.f16.f16.f32 "
        "{%0,%1,%2,%3}, {%4,%5,%6,%7}, {%8,%9}, {%0,%1,%2,%3};"
        : "+f"(c[0]), "+f"(c[1]), "+f"(c[2]), "+f"(c[3])
        : "r"(a0), "r"(a1), "r"(a2), "r"(a3), "r"(b0), "r"(b1));
}

__device__ __forceinline__ void ldsm4(unsigned& r0, unsigned& r1,
                                      unsigned& r2, unsigned& r3, unsigned addr)
{
    asm volatile("ldmatrix.sync.aligned.m8n8.x4.shared.b16 {%0,%1,%2,%3}, [%4];"
        : "=r"(r0), "=r"(r1), "=r"(r2), "=r"(r3) : "r"(addr));
}

__device__ __forceinline__ void ldsm4t(unsigned& r0, unsigned& r1,
                                       unsigned& r2, unsigned& r3, unsigned addr)
{
    asm volatile("ldmatrix.sync.aligned.m8n8.x4.trans.shared.b16 {%0,%1,%2,%3}, [%4];"
        : "=r"(r0), "=r"(r1), "=r"(r2), "=r"(r3) : "r"(addr));
}

__device__ __forceinline__ void cp16(unsigned smem, const void* gptr)
{
    asm volatile("cp.async.cg.shared.global [%0], [%1], 16;" :: "r"(smem), "l"(gptr));
}
__device__ __forceinline__ void cp_commit() { asm volatile("cp.async.commit_group;"); }
__device__ __forceinline__ void cp_wait0()  { asm volatile("cp.async.wait_group 0;"); }
__device__ __forceinline__ void cp_wait1()  { asm volatile("cp.async.wait_group 1;"); }

// ---------------------------------------------------------------------------
// Fused prep: regions 0-6 fp32->fp16 conversion; region 7 packs the mask into
// bits (bit=1 -> masked). Mask dtype sniffed per-block.
// ---------------------------------------------------------------------------
__global__ void prep_kernel(
    const float* __restrict__ s0, const float* __restrict__ s1,
    const float* __restrict__ s2, const float* __restrict__ s3,
    const float* __restrict__ s4, const float* __restrict__ s5,
    const float* __restrict__ s6, const void* __restrict__ mraw)
{
    if (blockIdx.y == 7) {
        __shared__ int s_u8;
        const int lane = threadIdx.x & 31;
        if (threadIdx.x == 0) s_u8 = 0;
        __syncthreads();
        {
            const unsigned int* mw = (const unsigned int*)mraw;
            int found = 0;
            for (int i = threadIdx.x; i < 16384; i += blockDim.x)
                if (mw[i] > 1u) { found = 1; break; }
            if (found) s_u8 = 1;
        }
        __syncthreads();
        const bool u8 = (s_u8 != 0);

        const int nwords = BB * SLQ * (SLK / 32);  // 262144 output words
        int gw = (blockIdx.x * blockDim.x + threadIdx.x) >> 5;
        const int stride = (gridDim.x * blockDim.x) >> 5;
        if (!u8) {
            const int nchunks = nwords / 4;        // 65536
            for (int ch = gw; ch < nchunks; ch += stride) {
                int4 v = ((const int4*)mraw)[ch * 32 + lane];
                unsigned nib = (v.x ? 1u : 0u) | (v.y ? 2u : 0u)
                             | (v.z ? 4u : 0u) | (v.w ? 8u : 0u);
                unsigned acc = nib << ((lane & 7) * 4);
                acc |= __shfl_xor_sync(0xffffffffu, acc, 1);
                acc |= __shfl_xor_sync(0xffffffffu, acc, 2);
                acc |= __shfl_xor_sync(0xffffffffu, acc, 4);
                if ((lane & 7) == 0) g_mbits[ch * 4 + (lane >> 3)] = acc;
            }
        } else {
            for (int w = gw; w < nwords; w += stride) {
                int idx = w * 32 + lane;
                int v = (int)((const unsigned char*)mraw)[idx];
                unsigned int bits = __ballot_sync(0xffffffffu, v != 0);
                if (lane == 0) g_mbits[w] = bits;
            }
        }
        return;
    }

    const float* src;
    __half* dst;
    int n;
    switch (blockIdx.y) {
        case 0: src = s0; dst = g_xq; n = MROWS * DM; break;
        case 1: src = s1; dst = g_xk; n = MROWS * DM; break;
        case 2: src = s2; dst = g_xv; n = MROWS * DM; break;
        case 3: src = s3; dst = g_wq; n = NH * DM * DH; break;
        case 4: src = s4; dst = g_wk; n = NH * DM * DH; break;
        case 5: src = s5; dst = g_wv; n = NH * DM * DH; break;
        default: src = s6; dst = g_wo; n = DM * DM; break;
    }
    int i = (blockIdx.x * blockDim.x + threadIdx.x) * 4;
    int stride = gridDim.x * blockDim.x * 4;
    for (; i < n; i += stride) {
        float4 v = *(const float4*)&src[i];
        *(uint2*)&dst[i] = make_uint2(pack2(v.x, v.y), pack2(v.z, v.w));
    }
}

// ---------------------------------------------------------------------------
// Projection GEMM (fp16 mma): C[h,b,l,e] = sum_d X[b,l,d]*W[h,d,e]
// ---------------------------------------------------------------------------
#define ASZ (128*72)
#define BSZ (64*136)
#define GEMM_SMEM ((2*ASZ + 2*BSZ) * 2)

__global__ __launch_bounds__(256, 2) void proj_kernel()
{
    extern __shared__ __half dsm[];
    __half* Asm = dsm;
    __half* Bsm = dsm + 2 * ASZ;

    const __half* __restrict__ X;
    const __half* __restrict__ W;
    __half* __restrict__ C;
    if (blockIdx.z == 0)      { X = g_xq; W = g_wq; C = g_qh; }
    else if (blockIdx.z == 1) { X = g_xk; W = g_wk; C = g_kh; }
    else                      { X = g_xv; W = g_wv; C = g_vh; }

    const int t = threadIdx.x;
    const int warp = t >> 5, lane = t & 31;
    const int g = lane >> 2, tq = lane & 3;
    const int wm = warp >> 2, wn = warp & 3;
    const int mBase = blockIdx.y * 128;
    const int h0 = blockIdx.x * 2;

    const int i8 = lane & 7, sel = lane >> 3;
    const int rowF = ((sel & 1) << 3) + i8;
    const int colF = (sel >> 1) << 3;
    const unsigned aSm = (unsigned)__cvta_generic_to_shared(Asm);
    const unsigned bSm = (unsigned)__cvta_generic_to_shared(Bsm);

    float acc[4][4][4];
    #pragma unroll
    for (int mt = 0; mt < 4; mt++)
        #pragma unroll
        for (int nt = 0; nt < 4; nt++)
            #pragma unroll
            for (int i = 0; i < 4; i++) acc[mt][nt][i] = 0.f;

    const int arow = t >> 3, aseg = (t & 7) * 8;
    const int brow = t >> 4, bseg = (t & 15) * 8;

    auto stage = [&](int kt, int buf) {
        #pragma unroll
        for (int it = 0; it < 4; it++) {
            int row = arow + it * 32;
            cp16(aSm + ((buf * 128 + row) * 72 + aseg) * 2,
                 &X[(size_t)(mBase + row) * DM + kt + aseg]);
        }
        #pragma unroll
        for (int it = 0; it < 4; it++) {
            int row = brow + it * 16;
            int head = h0 + (bseg >> 6), e = bseg & 63;
            cp16(bSm + ((buf * 64 + row) * 136 + bseg) * 2,
                 &W[((size_t)head * DM + kt + row) * DH + e]);
        }
        cp_commit();
    };

    stage(0, 0);
    const int NKT = DM / 64;  // 16
    for (int it = 0; it < NKT; it++) {
        cp_wait0();
        __syncthreads();
        if (it + 1 < NKT) stage((it + 1) * 64, (it + 1) & 1);
        const int abuf = (it & 1) * 128, bbuf = (it & 1) * 64;

        #pragma unroll
        for (int ks = 0; ks < 4; ks++) {
            unsigned af[4][4];
            #pragma unroll
            for (int mt = 0; mt < 4; mt++)
                ldsm4(af[mt][0], af[mt][1], af[mt][2], af[mt][3],
                      aSm + ((abuf + wm * 64 + mt * 16 + rowF) * 72 + ks * 16 + colF) * 2);
            #pragma unroll
            for (int ntp = 0; ntp < 2; ntp++) {
                unsigned b0, b1, b2, b3;
                ldsm4t(b0, b1, b2, b3,
                       bSm + ((bbuf + ks * 16 + rowF) * 136 + wn * 32 + ntp * 16 + colF) * 2);
                #pragma unroll
                for (int mt = 0; mt < 4; mt++) {
                    mma16816(acc[mt][ntp * 2],     af[mt][0], af[mt][1], af[mt][2], af[mt][3], b0, b1);
                    mma16816(acc[mt][ntp * 2 + 1], af[mt][0], af[mt][1], af[mt][2], af[mt][3], b2, b3);
                }
            }
        }
    }

    #pragma unroll
    for (int mt = 0; mt < 4; mt++) {
        int r0 = mBase + wm * 64 + mt * 16 + g;
        int r1 = r0 + 8;
        int b0i = r0 >> 11, l0 = r0 & 2047;
        int b1i = r1 >> 11, l1 = r1 & 2047;
        #pragma unroll
        for (int nt = 0; nt < 4; nt++) {
            int n = wn * 32 + nt * 8 + tq * 2;
            int head = h0 + (n >> 6), e = n & 63;
            __half* c0 = C + (((size_t)(head * BB + b0i) << 11) + l0) * DH;
            __half* c1 = C + (((size_t)(head * BB + b1i) << 11) + l1) * DH;
            *(unsigned*)&c0[e] = pack2(acc[mt][nt][0], acc[mt][nt][1]);
            *(unsigned*)&c1[e] = pack2(acc[mt][nt][2], acc[mt][nt][3]);
        }
    }
}

// ---------------------------------------------------------------------------
// Output projection: g_x = Ocat @ Wo + bo + resid (fp32 out)
// ---------------------------------------------------------------------------
__global__ __launch_bounds__(256, 2) void outproj_kernel(
    const float* __restrict__ resid, const float* __restrict__ bo)
{
    extern __shared__ __half dsm[];
    __half* Asm = dsm;
    __half* Bsm = dsm + 2 * ASZ;

    const int t = threadIdx.x;
    const int warp = t >> 5, lane = t & 31;
    const int g = lane >> 2, tq = lane & 3;
    const int wm = warp >> 2, wn = warp & 3;
    const int mBase = blockIdx.y * 128;
    const int nBase = blockIdx.x * 128;

    const int i8 = lane & 7, sel = lane >> 3;
    const int rowF = ((sel & 1) << 3) + i8;
    const int colF = (sel >> 1) << 3;
    const unsigned aSm = (unsigned)__cvta_generic_to_shared(Asm);
    const unsigned bSm = (unsigned)__cvta_generic_to_shared(Bsm);

    float acc[4][4][4];
    #pragma unroll
    for (int mt = 0; mt < 4; mt++)
        #pragma unroll
        for (int nt = 0; nt < 4; nt++)
            #pragma unroll
            for (int i = 0; i < 4; i++) acc[mt][nt][i] = 0.f;

    const int arow = t >> 3, aseg = (t & 7) * 8;
    const int brow = t >> 4, bseg = (t & 15) * 8;

    auto stage = [&](int kt, int buf) {
        const int kh = kt >> 6;
        #pragma unroll
        for (int it = 0; it < 4; it++) {
            int row = arow + it * 32;
            int m = mBase + row;
            int mb = m >> 11, ml = m & 2047;
            cp16(aSm + ((buf * 128 + row) * 72 + aseg) * 2,
                 &g_oh[(((size_t)(kh * BB + mb) << 11) + ml) * DH + aseg]);
        }
        #pragma unroll
        for (int it = 0; it < 4; it++) {
            int row = brow + it * 16;
            cp16(bSm + ((buf * 64 + row) * 136 + bseg) * 2,
                 &g_wo[(size_t)(kt + row) * DM + nBase + bseg]);
        }
        cp_commit();
    };

    stage(0, 0);
    const int NKT = DM / 64;
    for (int it = 0; it < NKT; it++) {
        cp_wait0();
        __syncthreads();
        if (it + 1 < NKT) stage((it + 1) * 64, (it + 1) & 1);
        const int abuf = (it & 1) * 128, bbuf = (it & 1) * 64;

        #pragma unroll
        for (int ks = 0; ks < 4; ks++) {
            unsigned af[4][4];
            #pragma unroll
            for (int mt = 0; mt < 4; mt++)
                ldsm4(af[mt][0], af[mt][1], af[mt][2], af[mt][3],
                      aSm + ((abuf + wm * 64 + mt * 16 + rowF) * 72 + ks * 16 + colF) * 2);
            #pragma unroll
            for (int ntp = 0; ntp < 2; ntp++) {
                unsigned b0, b1, b2, b3;
                ldsm4t(b0, b1, b2, b3,
                       bSm + ((bbuf + ks * 16 + rowF) * 136 + wn * 32 + ntp * 16 + colF) * 2);
                #pragma unroll
                for (int mt = 0; mt < 4; mt++) {
                    mma16816(acc[mt][ntp * 2],     af[mt][0], af[mt][1], af[mt][2], af[mt][3], b0, b1);
                    mma16816(acc[mt][ntp * 2 + 1], af[mt][0], af[mt][1], af[mt][2], af[mt][3], b2, b3);
                }
            }
        }
    }

    #pragma unroll
    for (int mt = 0; mt < 4; mt++) {
        int r0 = mBase + wm * 64 + mt * 16 + g;
        int r1 = r0 + 8;
        #pragma unroll
        for (int nt = 0; nt < 4; nt++) {
            int n = nBase + wn * 32 + nt * 8 + tq * 2;
            float2 bb = *(const float2*)&bo[n];
            float2 rA = *(const float2*)&resid[(size_t)r0 * DM + n];
            float2 rB = *(const float2*)&resid[(size_t)r1 * DM + n];
            *(float2*)&g_x[(size_t)r0 * DM + n] =
                make_float2(acc[mt][nt][0] + bb.x + rA.x, acc[mt][nt][1] + bb.y + rA.y);
            *(float2*)&g_x[(size_t)r1 * DM + n] =
                make_float2(acc[mt][nt][2] + bb.x + rB.x, acc[mt][nt][3] + bb.y + rB.y);
        }
    }
}

// ---------------------------------------------------------------------------
// Flash attention, software-pipelined: at iter i issue S(i), then PV(i-1)
// (independent of S(i) results), so tensor work overlaps the softmax chain.
// 4-deep KV circular buffers in dynamic smem; cp.async depth 2.
// ---------------------------------------------------------------------------
#define ATTN_BUF (64*72)                    // halves per K or V buffer
#define ATTN_SMEM (8 * ATTN_BUF * 2)        // 4 K + 4 V buffers = 73,728 B

__global__ __launch_bounds__(256, 2) void attn_kernel()
{
    extern __shared__ __half asmem[];
    const unsigned base = (unsigned)__cvta_generic_to_shared(asmem);

    const int t = threadIdx.x;
    const int warp = t >> 5, lane = t & 31;
    const int g = lane >> 2, tq = lane & 3;
    const int hb = blockIdx.y;
    const int b = hb & 1;
    const int qBase = blockIdx.x * 128;

    const __half* __restrict__ Q = g_qh + (size_t)hb * SLQ * DH;
    const __half* __restrict__ K = g_kh + (size_t)hb * SLK * DH;
    const __half* __restrict__ V = g_vh + (size_t)hb * SLK * DH;
    __half* __restrict__ O = g_oh + (size_t)hb * SLQ * DH;

    const int r0 = qBase + warp * 16 + g;
    const int r1 = r0 + 8;

    // Q fragments, pre-scaled by c = (1/8)*log2(e)
    const unsigned ch2 = 0x31C531C5u;
    unsigned qf[4][4];
    #pragma unroll
    for (int ks = 0; ks < 4; ks++) {
        qf[ks][0] = hmul2(*(const unsigned*)&Q[(size_t)r0 * DH + ks * 16 + 2 * tq], ch2);
        qf[ks][1] = hmul2(*(const unsigned*)&Q[(size_t)r1 * DH + ks * 16 + 2 * tq], ch2);
        qf[ks][2] = hmul2(*(const unsigned*)&Q[(size_t)r0 * DH + ks * 16 + 8 + 2 * tq], ch2);
        qf[ks][3] = hmul2(*(const unsigned*)&Q[(size_t)r1 * DH + ks * 16 + 8 + 2 * tq], ch2);
    }

    const int i8 = lane & 7, sel = lane >> 3;
    const int rowK = ((sel >> 1) << 3) + i8;
    const int colK = (sel & 1) << 3;
    const int rowV = ((sel & 1) << 3) + i8;
    const int colV = (sel >> 1) << 3;
    const unsigned kFrag = (rowK * 72 + colK) * 2;
    const unsigned vFrag = (rowV * 72 + colV) * 2;

    float oc[8][4];
    #pragma unroll
    for (int dt = 0; dt < 8; dt++)
        #pragma unroll
        for (int i = 0; i < 4; i++) oc[dt][i] = 0.f;
    float m0 = -1e30f, m1 = -1e30f, l0 = 0.f, l1 = 0.f;

    const unsigned* mb0 = &g_mbits[((size_t)(b << 11) + r0) * 64];
    const unsigned* mb1 = &g_mbits[((size_t)(b << 11) + r1) * 64];
    const int tq2 = tq * 2;

    const int srow = t >> 3, sseg = (t & 7) * 8;

    auto kbuf = [&](int i) { return base + ((unsigned)(i & 3) * ATTN_BUF) * 2u; };
    auto vbuf = [&](int i) { return base + ((unsigned)(4 + (i & 3)) * ATTN_BUF) * 2u; };

    auto stage = [&](int tile) {
        const int kb = tile * 64;
        const unsigned kB = kbuf(tile), vB = vbuf(tile);
        #pragma unroll
        for (int it = 0; it < 2; it++) {
            int row = srow + it * 32;
            cp16(kB + (row * 72 + sseg) * 2, &K[(size_t)(kb + row) * DH + sseg]);
            cp16(vB + (row * 72 + sseg) * 2, &V[(size_t)(kb + row) * DH + sseg]);
        }
        cp_commit();
    };

    stage(0);
    stage(1);

    unsigned pf[8][2];   // P fragments of previous tile (persist across iters)

    const int NT = SLK / 64;  // 32
    for (int it = 0; it < NT; it++) {
        if (it < NT - 1) cp_wait1(); else cp_wait0();
        __syncthreads();

        const unsigned kA = kbuf(it) + kFrag;
        const int kb = it * 64;

        // mask words early (complete under MMAs)
        uint2 w0 = *(const uint2*)&mb0[kb >> 5];
        uint2 w1 = *(const uint2*)&mb1[kb >> 5];

        // ---- S(it) ----
        float sc[8][4];
        #pragma unroll
        for (int nt = 0; nt < 8; nt++)
            #pragma unroll
            for (int i = 0; i < 4; i++) sc[nt][i] = 0.f;

        #pragma unroll
        for (int ks = 0; ks < 4; ks++) {
            #pragma unroll
            for (int ntp = 0; ntp < 4; ntp++) {
                unsigned b0, b1, b2, b3;
                ldsm4(b0, b1, b2, b3, kA + (ntp * 16 * 72 + ks * 16) * 2);
                mma16816(sc[ntp * 2],     qf[ks][0], qf[ks][1], qf[ks][2], qf[ks][3], b0, b1);
                mma16816(sc[ntp * 2 + 1], qf[ks][0], qf[ks][1], qf[ks][2], qf[ks][3], b2, b3);
            }
        }

        // ---- prefetch tile it+2 ----
        if (it + 2 < NT) stage(it + 2);

        // ---- PV(it-1): independent of S(it) results; overlaps softmax wait ----
        if (it > 0) {
            const unsigned vA = vbuf(it - 1) + vFrag;
            #pragma unroll
            for (int ks = 0; ks < 4; ks++) {
                unsigned a0 = pf[2 * ks][0], a1 = pf[2 * ks][1];
                unsigned a2 = pf[2 * ks + 1][0], a3 = pf[2 * ks + 1][1];
                #pragma unroll
                for (int dtp = 0; dtp < 4; dtp++) {
                    unsigned b0, b1, b2, b3;
                    ldsm4t(b0, b1, b2, b3, vA + (ks * 16 * 72 + dtp * 16) * 2);
                    mma16816(oc[dtp * 2],     a0, a1, a2, a3, b0, b1);
                    mma16816(oc[dtp * 2 + 1], a0, a1, a2, a3, b2, b3);
                }
            }
        }

        // ---- softmax(it) ----
        float mx0 = -1e30f, mx1 = -1e30f;
        #pragma unroll
        for (int nt = 0; nt < 8; nt++) {
            mx0 = fmaxf(mx0, fmaxf(sc[nt][0], sc[nt][1]));
            mx1 = fmaxf(mx1, fmaxf(sc[nt][2], sc[nt][3]));
        }
        mx0 = fmaxf(mx0, __shfl_xor_sync(0xffffffffu, mx0, 1));
        mx0 = fmaxf(mx0, __shfl_xor_sync(0xffffffffu, mx0, 2));
        mx1 = fmaxf(mx1, __shfl_xor_sync(0xffffffffu, mx1, 1));
        mx1 = fmaxf(mx1, __shfl_xor_sync(0xffffffffu, mx1, 2));

        float newm0 = fmaxf(m0, mx0), newm1 = fmaxf(m1, mx1);
        bool nochg = (newm0 == m0) && (newm1 == m1);
        bool allno = __all_sync(0xffffffffu, nochg);
        float al0 = 1.f, al1 = 1.f;
        if (!allno) {
            al0 = ex2f(m0 - newm0);
            al1 = ex2f(m1 - newm1);
            m0 = newm0; m1 = newm1;
        }

        unsigned long long mq0 =
            ((unsigned long long)w0.x | ((unsigned long long)w0.y << 32)) >> tq2;
        unsigned long long mq1 =
            ((unsigned long long)w1.x | ((unsigned long long)w1.y << 32)) >> tq2;

        __half2 hs0 = __floats2half2_rn(0.f, 0.f);
        __half2 hs1 = hs0;
        #pragma unroll
        for (int nt = 0; nt < 8; nt++) {
            unsigned bb0 = (unsigned)(mq0 >> (nt * 8)) & 3u;
            unsigned bb1 = (unsigned)(mq1 >> (nt * 8)) & 3u;
            unsigned mm0v = 0x3C003C00u;
            if (bb0 & 1u) mm0v &= 0xFFFF0000u;
            if (bb0 & 2u) mm0v &= 0x0000FFFFu;
            unsigned mm1v = 0x3C003C00u;
            if (bb1 & 1u) mm1v &= 0xFFFF0000u;
            if (bb1 & 2u) mm1v &= 0x0000FFFFu;
            pf[nt][0] = hmul2(ex2h2(pack2(sc[nt][0] - newm0, sc[nt][1] - newm0)), mm0v);
            pf[nt][1] = hmul2(ex2h2(pack2(sc[nt][2] - newm1, sc[nt][3] - newm1)), mm1v);
            hs0 = __hadd2(hs0, *(__half2*)&pf[nt][0]);
            hs1 = __hadd2(hs1, *(__half2*)&pf[nt][1]);
        }
        float2 f0 = __half22float2(hs0);
        float2 f1 = __half22float2(hs1);
        float rs0 = f0.x + f0.y, rs1 = f1.x + f1.y;
        rs0 += __shfl_xor_sync(0xffffffffu, rs0, 1);
        rs0 += __shfl_xor_sync(0xffffffffu, rs0, 2);
        rs1 += __shfl_xor_sync(0xffffffffu, rs1, 1);
        rs1 += __shfl_xor_sync(0xffffffffu, rs1, 2);
        l0 = l0 * al0 + rs0;
        l1 = l1 * al1 + rs1;

        // rescale oc AFTER PV(it-1) accumulation (scoreboard orders vs mma)
        if (!allno) {
            #pragma unroll
            for (int dt = 0; dt < 8; dt++) {
                oc[dt][0] *= al0; oc[dt][1] *= al0;
                oc[dt][2] *= al1; oc[dt][3] *= al1;
            }
        }
    }

    // drain: PV(NT-1)
    {
        const unsigned vA = vbuf(NT - 1) + vFrag;
        #pragma unroll
        for (int ks = 0; ks < 4; ks++) {
            unsigned a0 = pf[2 * ks][0], a1 = pf[2 * ks][1];
            unsigned a2 = pf[2 * ks + 1][0], a3 = pf[2 * ks + 1][1];
            #pragma unroll
            for (int dtp = 0; dtp < 4; dtp++) {
                unsigned b0, b1, b2, b3;
                ldsm4t(b0, b1, b2, b3, vA + (ks * 16 * 72 + dtp * 16) * 2);
                mma16816(oc[dtp * 2],     a0, a1, a2, a3, b0, b1);
                mma16816(oc[dtp * 2 + 1], a0, a1, a2, a3, b2, b3);
            }
        }
    }

    float inv0 = 1.f / l0, inv1 = 1.f / l1;
    #pragma unroll
    for (int dt = 0; dt < 8; dt++) {
        int d = dt * 8 + tq * 2;
        *(unsigned*)&O[(size_t)r0 * DH + d] = pack2(oc[dt][0] * inv0, oc[dt][1] * inv0);
        *(unsigned*)&O[(size_t)r1 * DH + d] = pack2(oc[dt][2] * inv1, oc[dt][3] * inv1);
    }
}

// ---------------------------------------------------------------------------
// LayerNorm (ddof=1, eps on std)
// ---------------------------------------------------------------------------
__global__ __launch_bounds__(256) void ln_kernel(
    const float* __restrict__ gamma, const float* __restrict__ beta,
    float* __restrict__ out)
{
    __shared__ float red[8];
    const int row = blockIdx.x;
    const int t = threadIdx.x;
    const float* x = g_x + (size_t)row * DM;

    float4 v = *(const float4*)&x[t * 4];
    float s = v.x + v.y + v.z + v.w;
    #pragma unroll
    for (int sft = 16; sft >= 1; sft >>= 1)
        s += __shfl_xor_sync(0xffffffffu, s, sft);
    if ((t & 31) == 0) red[t >> 5] = s;
    __syncthreads();
    float tot = 0.f;
    #pragma unroll
    for (int w = 0; w < 8; w++) tot += red[w];
    float mean = tot * (1.0f / DM);
    __syncthreads();

    float d0 = v.x - mean, d1 = v.y - mean, d2 = v.z - mean, d3 = v.w - mean;
    float sq = d0 * d0 + d1 * d1 + d2 * d2 + d3 * d3;
    #pragma unroll
    for (int sft = 16; sft >= 1; sft >>= 1)
        sq += __shfl_xor_sync(0xffffffffu, sq, sft);
    if ((t & 31) == 0) red[t >> 5] = sq;
    __syncthreads();
    float sqt = 0.f;
    #pragma unroll
    for (int w = 0; w < 8; w++) sqt += red[w];
    float stdv = sqrtf(sqt * (1.0f / (DM - 1)));
    float inv = 1.0f / (stdv + 1e-3f);

    float4 gm = *(const float4*)&gamma[t * 4];
    float4 be = *(const float4*)&beta[t * 4];
    float4 o;
    o.x = d0 * inv * gm.x + be.x;
    o.y = d1 * inv * gm.y + be.y;
    o.z = d2 * inv * gm.z + be.z;
    o.w = d3 * inv * gm.w + be.w;
    *(float4*)&out[(size_t)row * DM + t * 4] = o;
}

// ---------------------------------------------------------------------------
extern "C" void kernel_launch(void* const* d_in, const int* in_sizes, int n_in,
                              void* d_out, int out_size)
{
    const float* v_in  = (const float*)d_in[0];
    const float* k_in  = (const float*)d_in[1];
    const float* q_in  = (const float*)d_in[2];
    const void*  mask  = d_in[3];
    const float* w_q   = (const float*)d_in[4];
    const float* w_k   = (const float*)d_in[5];
    const float* w_v   = (const float*)d_in[6];
    const float* w_o   = (const float*)d_in[7];
    const float* b_o   = (const float*)d_in[8];
    const float* gamma = (const float*)d_in[9];
    const float* beta  = (const float*)d_in[10];
    float* out = (float*)d_out;

    cudaFuncSetAttribute(proj_kernel, cudaFuncAttributeMaxDynamicSharedMemorySize, GEMM_SMEM);
    cudaFuncSetAttribute(outproj_kernel, cudaFuncAttributeMaxDynamicSharedMemorySize, GEMM_SMEM);
    cudaFuncSetAttribute(attn_kernel, cudaFuncAttributeMaxDynamicSharedMemorySize, ATTN_SMEM);

    prep_kernel<<<dim3(384, 8), 256>>>(q_in, k_in, v_in, w_q, w_k, w_v, w_o, mask);

    proj_kernel<<<dim3(NH / 2, MROWS / 128, 3), 256, GEMM_SMEM>>>();
    attn_kernel<<<dim3(SLQ / 128, NH * BB), 256, ATTN_SMEM>>>();
    outproj_kernel<<<dim3(DM / 128, MROWS / 128), 256, GEMM_SMEM>>>(k_in, b_o);
    ln_kernel<<<MROWS, 256>>>(gamma, beta, out);
}